// round 2
// baseline (speedup 1.0000x reference)
#include <cuda_runtime.h>
#include <cuda_fp16.h>
#include <cstdint>

// ============================================================================
// LSTMCell for GB300 — sm_103 (non-'a') compatible path.
//   tcgen05 is unavailable (harness compiles via compute_103 virtual arch),
//   so: fp16 mma.sync.m16n8k16 + cp.async.bulk (1D TMA) + mbarrier pipeline.
//
//   Pass 1: fp32 -> fp16, pre-tiled + SW128-swizzled scratch
//           A = [x|h]  as [32 mtile][64 kc][128 m][128B row]
//           B = [Wih|Whh] as [64 ntile][64 kc][128 n][128B row]
//   Pass 2: GEMM 128x128x64-tile pipeline -> fp32 pre-activations g_C
//   Pass 3: elementwise LSTM gates -> h_next, c_next, go
// ============================================================================

#define DINLINE __device__ __forceinline__

__device__ __align__(1024) __half g_Ah[4096UL * 4096];   // 32 MB
__device__ __align__(1024) __half g_Bh[8192UL * 4096];   // 64 MB
__device__ __align__(1024) float  g_C [4096UL * 8192];   // 128 MB

// ------------------------------- helpers -----------------------------------
DINLINE uint32_t smem_u32(const void* p) {
    uint32_t a;
    asm("{ .reg .u64 t; cvta.to.shared.u64 t, %1; cvt.u32.u64 %0, t; }"
        : "=r"(a) : "l"(p));
    return a;
}

DINLINE void mbar_init(uint32_t a, uint32_t cnt) {
    asm volatile("mbarrier.init.shared.b64 [%0], %1;" :: "r"(a), "r"(cnt) : "memory");
}
DINLINE void mbar_expect(uint32_t a, uint32_t tx) {
    asm volatile("mbarrier.arrive.expect_tx.shared.b64 _, [%0], %1;"
                 :: "r"(a), "r"(tx) : "memory");
}
DINLINE void mbar_wait(uint32_t mbar, uint32_t parity) {
    uint32_t done;
    asm volatile(
        "{\n .reg .pred p;\n"
        " mbarrier.try_wait.parity.acquire.cta.shared::cta.b64 p, [%1], %2;\n"
        " selp.b32 %0, 1, 0, p;\n}"
        : "=r"(done) : "r"(mbar), "r"(parity) : "memory");
    if (!done) {
        asm volatile(
            "{\n .reg .pred P1;\n"
            "WL%=:\n"
            " mbarrier.try_wait.parity.acquire.cta.shared::cta.b64 P1, [%0], %1, 0x989680;\n"
            " @P1 bra.uni WD%=;\n"
            " bra.uni WL%=;\n"
            "WD%=:\n}"
            :: "r"(mbar), "r"(parity) : "memory");
    }
}

DINLINE void bulk_g2s(uint32_t dst, const void* src, uint32_t bytes, uint32_t mbar) {
    asm volatile(
        "cp.async.bulk.shared::cluster.global.mbarrier::complete_tx::bytes [%0], [%1], %2, [%3];"
        :: "r"(dst), "l"(src), "r"(bytes), "r"(mbar) : "memory");
}

DINLINE float sigf(float x) { return 1.0f / (1.0f + expf(-x)); }

// ============================================================================
// Pass 1: convert + tile + swizzle.  One thread = one 16B chunk (8 halves).
//   t bits: [c:3][m:7][kc:6][tile:5or6]
//   dst byte = (t>>3)*128 + ((c ^ (m&7)) << 4)
// ============================================================================
__global__ __launch_bounds__(256)
void cvt_pack(const float* __restrict__ a, const float* __restrict__ b, int which)
{
    const uint32_t t = blockIdx.x * 256u + threadIdx.x;
    const uint32_t c = t & 7u;
    const uint32_t m = (t >> 3) & 127u;
    const uint32_t k = ((t >> 10) & 63u) * 64u + c * 8u;
    const size_t srow = (size_t)((t >> 16) * 128u + m) * 2048;

    const float* src = (k < 2048u) ? (a + srow + k) : (b + srow + (k - 2048u));
    float4 v0 = *reinterpret_cast<const float4*>(src);
    float4 v1 = *reinterpret_cast<const float4*>(src + 4);

    __half2 h0 = __floats2half2_rn(v0.x, v0.y);
    __half2 h1 = __floats2half2_rn(v0.z, v0.w);
    __half2 h2 = __floats2half2_rn(v1.x, v1.y);
    __half2 h3 = __floats2half2_rn(v1.z, v1.w);
    uint4 out;
    out.x = *reinterpret_cast<uint32_t*>(&h0);
    out.y = *reinterpret_cast<uint32_t*>(&h1);
    out.z = *reinterpret_cast<uint32_t*>(&h2);
    out.w = *reinterpret_cast<uint32_t*>(&h3);

    unsigned char* dst = (unsigned char*)(which ? (void*)g_Bh : (void*)g_Ah);
    *reinterpret_cast<uint4*>(dst + ((size_t)(t >> 3) << 7) + ((c ^ (m & 7u)) << 4)) = out;
}

// ============================================================================
// Pass 2: GEMM.  C[4096, 8192] = A[4096,4096] @ B^T,  fp16 in / fp32 out.
//   CTA tile 128x128, BK=64 halves (128B rows), 3-stage bulk-copy pipeline.
//   8 warps: 2(M) x 4(N); warp tile 64x32; mma m16n8k16.
// ============================================================================
static constexpr int TILE_BYTES  = 16384;                 // 128 x 128B
static constexpr int STAGE_BYTES = 2 * TILE_BYTES;        // A + B
static constexpr int STAGES      = 3;
static constexpr int KITERS      = 64;                    // 4096 / 64
static constexpr int SMEM_ALLOC  = STAGES * STAGE_BYTES + 1024;

__global__ __launch_bounds__(256, 2)
void gemm_kernel()
{
    extern __shared__ unsigned char smraw[];
    __shared__ __align__(8) unsigned long long mbar_s[STAGES];

    const int tid  = threadIdx.x;
    const int lane = tid & 31;
    const int w    = tid >> 5;
    const int wm   = w & 1;        // 0..1  (M)
    const int wn   = w >> 1;       // 0..3  (N)
    const int mtile = blockIdx.x & 31;
    const int ntile = blockIdx.x >> 5;

    const uint32_t smb  = (smem_u32(smraw) + 1023u) & ~1023u;
    const uint32_t mbb  = smem_u32(&mbar_s[0]);

    if (tid == 0) {
        mbar_init(mbb + 0, 1);
        mbar_init(mbb + 8, 1);
        mbar_init(mbb + 16, 1);
    }
    __syncthreads();

    const uint64_t gA = (uint64_t)(const void*)g_Ah + (uint64_t)(mtile * 64) * TILE_BYTES;
    const uint64_t gB = (uint64_t)(const void*)g_Bh + (uint64_t)(ntile * 64) * TILE_BYTES;

    auto produce = [&](int it, int st) {
        const uint32_t mb = mbb + st * 8;
        mbar_expect(mb, (uint32_t)STAGE_BYTES);
        bulk_g2s(smb + st * STAGE_BYTES,              (const void*)(gA + (uint64_t)it * TILE_BYTES),
                 TILE_BYTES, mb);
        bulk_g2s(smb + st * STAGE_BYTES + TILE_BYTES, (const void*)(gB + (uint64_t)it * TILE_BYTES),
                 TILE_BYTES, mb);
    };
    if (tid == 0) { produce(0, 0); produce(1, 1); produce(2, 2); }

    // per-thread fragment address components (byte offsets inside a 16KB tile)
    uint32_t arow[4], brow[4], cxA[4], cxB[4];
    #pragma unroll
    for (int mi = 0; mi < 4; mi++)
        arow[mi] = (uint32_t)((wm * 64 + mi * 16 + ((lane >> 3) & 1) * 8 + (lane & 7)) << 7);
    #pragma unroll
    for (int ni = 0; ni < 4; ni++)
        brow[ni] = (uint32_t)(TILE_BYTES + ((wn * 32 + ni * 8 + (lane & 7)) << 7));
    #pragma unroll
    for (int ks = 0; ks < 4; ks++) {
        cxA[ks] = (uint32_t)((((2 * ks + (lane >> 4)) ^ (lane & 7)) << 4));
        cxB[ks] = (uint32_t)((((2 * ks + ((lane >> 3) & 1)) ^ (lane & 7)) << 4));
    }

    float acc[4][4][4];
    #pragma unroll
    for (int mi = 0; mi < 4; mi++)
        #pragma unroll
        for (int ni = 0; ni < 4; ni++)
            #pragma unroll
            for (int r = 0; r < 4; r++) acc[mi][ni][r] = 0.0f;

    int st = 0;
    uint32_t par = 0;

    for (int it = 0; it < KITERS; it++) {
        mbar_wait(mbb + st * 8, par);
        const uint32_t base = smb + st * STAGE_BYTES;

        #pragma unroll
        for (int ks = 0; ks < 4; ks++) {
            uint32_t b0[4], b1[4];
            #pragma unroll
            for (int ni = 0; ni < 4; ni++)
                asm volatile("ldmatrix.sync.aligned.m8n8.x2.shared.b16 {%0,%1}, [%2];"
                             : "=r"(b0[ni]), "=r"(b1[ni])
                             : "r"(base + brow[ni] + cxB[ks]));
            #pragma unroll
            for (int mi = 0; mi < 4; mi++) {
                uint32_t a0, a1, a2, a3;
                asm volatile("ldmatrix.sync.aligned.m8n8.x4.shared.b16 {%0,%1,%2,%3}, [%4];"
                             : "=r"(a0), "=r"(a1), "=r"(a2), "=r"(a3)
                             : "r"(base + arow[mi] + cxA[ks]));
                #pragma unroll
                for (int ni = 0; ni < 4; ni++)
                    asm volatile(
                        "mma.sync.aligned.m16n8k16.row.col.f32.f16.f16.f32 "
                        "{%0,%1,%2,%3}, {%4,%5,%6,%7}, {%8,%9}, {%0,%1,%2,%3};"
                        : "+f"(acc[mi][ni][0]), "+f"(acc[mi][ni][1]),
                          "+f"(acc[mi][ni][2]), "+f"(acc[mi][ni][3])
                        : "r"(a0), "r"(a1), "r"(a2), "r"(a3),
                          "r"(b0[ni]), "r"(b1[ni]));
            }
        }

        __syncthreads();                       // all warps done reading stage st
        if (tid == 0 && it + STAGES < KITERS) produce(it + STAGES, st);
        if (++st == STAGES) { st = 0; par ^= 1; }
    }

    // ---- write fp32 pre-activations ----
    #pragma unroll
    for (int mi = 0; mi < 4; mi++) {
        const int r0 = mtile * 128 + wm * 64 + mi * 16 + (lane >> 2);
        #pragma unroll
        for (int ni = 0; ni < 4; ni++) {
            const int c0 = ntile * 128 + wn * 32 + ni * 8 + (lane & 3) * 2;
            *reinterpret_cast<float2*>(g_C + (size_t)r0 * 8192 + c0) =
                make_float2(acc[mi][ni][0], acc[mi][ni][1]);
            *reinterpret_cast<float2*>(g_C + (size_t)(r0 + 8) * 8192 + c0) =
                make_float2(acc[mi][ni][2], acc[mi][ni][3]);
        }
    }
}

// ============================================================================
// Pass 3: elementwise LSTM cell.  One thread = 4 h-columns (float4).
// ============================================================================
__global__ __launch_bounds__(256)
void lstm_epilogue(const float* __restrict__ Bv, const float* __restrict__ Cin,
                   float* __restrict__ Oh, float* __restrict__ Oc, float* __restrict__ Og)
{
    const uint32_t t = blockIdx.x * 256u + threadIdx.x;   // 2^21 threads
    const uint32_t j4 = t & 511u;
    const size_t m = t >> 9;

    const float4* Crow = reinterpret_cast<const float4*>(g_C + m * 8192);
    float4 gf = Crow[j4], gi = Crow[512 + j4], gs = Crow[1024 + j4], go = Crow[1536 + j4];

    const float4* B4 = reinterpret_cast<const float4*>(Bv);
    float4 bf = B4[j4], bi = B4[512 + j4], bs = B4[1024 + j4], bo = B4[1536 + j4];
    float4 cc = reinterpret_cast<const float4*>(Cin)[m * 512 + j4];

    float4 hn, cn, oo;
    {
        float f = sigf(gf.x + bf.x), i = sigf(gi.x + bi.x);
        float s = tanhf(gs.x + bs.x), o = sigf(go.x + bo.x);
        cn.x = f * cc.x + i * s; hn.x = o * tanhf(cn.x); oo.x = o;
    }
    {
        float f = sigf(gf.y + bf.y), i = sigf(gi.y + bi.y);
        float s = tanhf(gs.y + bs.y), o = sigf(go.y + bo.y);
        cn.y = f * cc.y + i * s; hn.y = o * tanhf(cn.y); oo.y = o;
    }
    {
        float f = sigf(gf.z + bf.z), i = sigf(gi.z + bi.z);
        float s = tanhf(gs.z + bs.z), o = sigf(go.z + bo.z);
        cn.z = f * cc.z + i * s; hn.z = o * tanhf(cn.z); oo.z = o;
    }
    {
        float f = sigf(gf.w + bf.w), i = sigf(gi.w + bi.w);
        float s = tanhf(gs.w + bs.w), o = sigf(go.w + bo.w);
        cn.w = f * cc.w + i * s; hn.w = o * tanhf(cn.w); oo.w = o;
    }

    reinterpret_cast<float4*>(Oh)[m * 512 + j4] = hn;
    reinterpret_cast<float4*>(Oc)[m * 512 + j4] = cn;
    reinterpret_cast<float4*>(Og)[m * 512 + j4] = oo;
}

// ============================================================================
// launch
// ============================================================================
extern "C" void kernel_launch(void* const* d_in, const int* in_sizes, int n_in,
                              void* d_out, int out_size)
{
    const float* x    = (const float*)d_in[0];
    const float* h    = (const float*)d_in[1];
    const float* c    = (const float*)d_in[2];
    /* d_in[3] = o, unused by the reference computation */
    const float* w_ih = (const float*)d_in[4];
    const float* w_hh = (const float*)d_in[5];
    const float* b    = (const float*)d_in[6];
    float* out = (float*)d_out;

    cudaFuncSetAttribute(gemm_kernel,
                         cudaFuncAttributeMaxDynamicSharedMemorySize, SMEM_ALLOC);

    cvt_pack<<<8192,  256>>>(x,    h,    0);
    cvt_pack<<<16384, 256>>>(w_ih, w_hh, 1);
    gemm_kernel<<<2048, 256, SMEM_ALLOC>>>();

    float* out_h  = out;
    float* out_c  = out + (size_t)4096 * 2048;
    float* out_go = out + (size_t)2 * 4096 * 2048;
    lstm_epilogue<<<8192, 256>>>(b, c, out_h, out_c, out_go);
}

// round 3
// speedup vs baseline: 1.0112x; 1.0112x over previous
#include <cuda_runtime.h>
#include <cuda_fp16.h>
#include <cstdint>

// ============================================================================
// LSTMCell for GB300 — sm_103 (non-'a') path: fp16 mma.sync + cp.async.bulk.
//
//   Pass 1: fp32 -> fp16 (RN), pre-tiled + SW128-swizzled scratch.
//           A = [x|h]      as [32 mtile][64 kc][128 m][128B]
//           B = [Wih|Whh]  as [64 ntile][64 kc][128 packed-n][128B]
//           packed-n interleaves gates: n = gate*32 + col32 within a tile,
//           so one CTA tile (128 N) = 4 gates x 32 h-cols (gate-complete).
//   Pass 2: GEMM 128x128x64-iter pipeline + FUSED LSTM epilogue
//           (no fp32 pre-activation round-trip through DRAM).
// ============================================================================

#define DINLINE __device__ __forceinline__

__device__ __align__(1024) __half g_Ah[4096UL * 4096];   // 32 MB
__device__ __align__(1024) __half g_Bh[8192UL * 4096];   // 64 MB

// ------------------------------- helpers -----------------------------------
DINLINE uint32_t smem_u32(const void* p) {
    uint32_t a;
    asm("{ .reg .u64 t; cvta.to.shared.u64 t, %1; cvt.u32.u64 %0, t; }"
        : "=r"(a) : "l"(p));
    return a;
}

DINLINE void mbar_init(uint32_t a, uint32_t cnt) {
    asm volatile("mbarrier.init.shared.b64 [%0], %1;" :: "r"(a), "r"(cnt) : "memory");
}
DINLINE void mbar_expect(uint32_t a, uint32_t tx) {
    asm volatile("mbarrier.arrive.expect_tx.shared.b64 _, [%0], %1;"
                 :: "r"(a), "r"(tx) : "memory");
}
DINLINE void mbar_wait(uint32_t mbar, uint32_t parity) {
    uint32_t done;
    asm volatile(
        "{\n .reg .pred p;\n"
        " mbarrier.try_wait.parity.acquire.cta.shared::cta.b64 p, [%1], %2;\n"
        " selp.b32 %0, 1, 0, p;\n}"
        : "=r"(done) : "r"(mbar), "r"(parity) : "memory");
    if (!done) {
        asm volatile(
            "{\n .reg .pred P1;\n"
            "WL%=:\n"
            " mbarrier.try_wait.parity.acquire.cta.shared::cta.b64 P1, [%0], %1, 0x989680;\n"
            " @P1 bra.uni WD%=;\n"
            " bra.uni WL%=;\n"
            "WD%=:\n}"
            :: "r"(mbar), "r"(parity) : "memory");
    }
}

DINLINE void bulk_g2s(uint32_t dst, const void* src, uint32_t bytes, uint32_t mbar) {
    asm volatile(
        "cp.async.bulk.shared::cluster.global.mbarrier::complete_tx::bytes [%0], [%1], %2, [%3];"
        :: "r"(dst), "l"(src), "r"(bytes), "r"(mbar) : "memory");
}

DINLINE float sigf(float x) { return 1.0f / (1.0f + expf(-x)); }

// ============================================================================
// Pass 1: convert + tile + swizzle.  One thread = one 16B chunk (8 halves).
//   t bits: [c:3][m:7][kc:6][tile:rest]
//   For W (which=1): packed row (tile*128+m) pulls gate-interleaved source:
//       gate = m>>5, c32 = m&31, src_row = gate*2048 + tile*32 + c32
// ============================================================================
__global__ __launch_bounds__(256)
void cvt_pack(const float* __restrict__ a, const float* __restrict__ b, int which)
{
    const uint32_t t = blockIdx.x * 256u + threadIdx.x;
    const uint32_t c = t & 7u;
    const uint32_t m = (t >> 3) & 127u;
    const uint32_t k = ((t >> 10) & 63u) * 64u + c * 8u;
    const uint32_t tile = t >> 16;

    uint32_t src_row;
    if (which) src_row = ((m >> 5) << 11) + tile * 32u + (m & 31u);
    else       src_row = tile * 128u + m;

    const size_t srow = (size_t)src_row * 2048;
    const float* src = (k < 2048u) ? (a + srow + k) : (b + srow + (k - 2048u));
    float4 v0 = *reinterpret_cast<const float4*>(src);
    float4 v1 = *reinterpret_cast<const float4*>(src + 4);

    __half2 h0 = __floats2half2_rn(v0.x, v0.y);
    __half2 h1 = __floats2half2_rn(v0.z, v0.w);
    __half2 h2 = __floats2half2_rn(v1.x, v1.y);
    __half2 h3 = __floats2half2_rn(v1.z, v1.w);
    uint4 out;
    out.x = *reinterpret_cast<uint32_t*>(&h0);
    out.y = *reinterpret_cast<uint32_t*>(&h1);
    out.z = *reinterpret_cast<uint32_t*>(&h2);
    out.w = *reinterpret_cast<uint32_t*>(&h3);

    unsigned char* dst = (unsigned char*)(which ? (void*)g_Bh : (void*)g_Ah);
    *reinterpret_cast<uint4*>(dst + ((size_t)(t >> 3) << 7) + ((c ^ (m & 7u)) << 4)) = out;
}

// ============================================================================
// Pass 2: fused GEMM + LSTM cell.
//   CTA tile 128(M) x 128(packed N = 4 gates x 32 h-cols), BK=64.
//   8 warps 2(M) x 4(N); warp tile 64x32; mma m16n8k16 fp16->fp32.
// ============================================================================
static constexpr int TILE_BYTES  = 16384;                 // 128 x 128B
static constexpr int STAGE_BYTES = 2 * TILE_BYTES;        // A + B
static constexpr int STAGES      = 3;
static constexpr int KITERS      = 64;                    // 4096 / 64
static constexpr int SMEM_ALLOC  = STAGES * STAGE_BYTES + 1024;

__global__ __launch_bounds__(256, 2)
void lstm_gemm(const float* __restrict__ Bv, const float* __restrict__ Cin,
               float* __restrict__ Oh, float* __restrict__ Oc, float* __restrict__ Og)
{
    extern __shared__ unsigned char smraw[];
    __shared__ __align__(8) unsigned long long mbar_s[STAGES];
    __shared__ float s_bias[128];

    const int tid  = threadIdx.x;
    const int lane = tid & 31;
    const int w    = tid >> 5;
    const int wm   = w & 1;        // 0..1  (M)
    const int wn   = w >> 1;       // 0..3  (N)
    const int mtile = blockIdx.x & 31;   // 0..31
    const int ntile = blockIdx.x >> 5;   // 0..63 (h-col block of 32)

    const uint32_t smb = (smem_u32(smraw) + 1023u) & ~1023u;
    unsigned char* smal = smraw + (smb - smem_u32(smraw));
    const uint32_t mbb = smem_u32(&mbar_s[0]);

    if (tid == 0) {
        mbar_init(mbb + 0, 1);
        mbar_init(mbb + 8, 1);
        mbar_init(mbb + 16, 1);
    }
    if (tid < 128)
        s_bias[tid] = Bv[(size_t)((tid >> 5) << 11) + (size_t)ntile * 32 + (tid & 31)];
    __syncthreads();

    const uint64_t gA = (uint64_t)(const void*)g_Ah + (uint64_t)(mtile * 64) * TILE_BYTES;
    const uint64_t gB = (uint64_t)(const void*)g_Bh + (uint64_t)(ntile * 64) * TILE_BYTES;

    auto produce = [&](int it, int st) {
        const uint32_t mb = mbb + st * 8;
        mbar_expect(mb, (uint32_t)STAGE_BYTES);
        bulk_g2s(smb + st * STAGE_BYTES,
                 (const void*)(gA + (uint64_t)it * TILE_BYTES), TILE_BYTES, mb);
        bulk_g2s(smb + st * STAGE_BYTES + TILE_BYTES,
                 (const void*)(gB + (uint64_t)it * TILE_BYTES), TILE_BYTES, mb);
    };
    if (tid == 0) { produce(0, 0); produce(1, 1); produce(2, 2); }

    // fragment address components (byte offsets inside a 16KB tile)
    uint32_t arow[4], brow[4], cxA[4], cxB[4];
    #pragma unroll
    for (int mi = 0; mi < 4; mi++)
        arow[mi] = (uint32_t)((wm * 64 + mi * 16 + ((lane >> 3) & 1) * 8 + (lane & 7)) << 7);
    #pragma unroll
    for (int ni = 0; ni < 4; ni++)
        brow[ni] = (uint32_t)(TILE_BYTES + ((wn * 32 + ni * 8 + (lane & 7)) << 7));
    #pragma unroll
    for (int ks = 0; ks < 4; ks++) {
        cxA[ks] = (uint32_t)((((2 * ks + (lane >> 4)) ^ (lane & 7)) << 4));
        cxB[ks] = (uint32_t)((((2 * ks + ((lane >> 3) & 1)) ^ (lane & 7)) << 4));
    }

    float acc[4][4][4];
    #pragma unroll
    for (int mi = 0; mi < 4; mi++)
        #pragma unroll
        for (int ni = 0; ni < 4; ni++)
            #pragma unroll
            for (int r = 0; r < 4; r++) acc[mi][ni][r] = 0.0f;

    int st = 0;
    uint32_t par = 0;

    for (int it = 0; it < KITERS; it++) {
        mbar_wait(mbb + st * 8, par);
        const uint32_t base = smb + st * STAGE_BYTES;

        #pragma unroll
        for (int ks = 0; ks < 4; ks++) {
            uint32_t b0[4], b1[4];
            #pragma unroll
            for (int ni = 0; ni < 4; ni++)
                asm volatile("ldmatrix.sync.aligned.m8n8.x2.shared.b16 {%0,%1}, [%2];"
                             : "=r"(b0[ni]), "=r"(b1[ni])
                             : "r"(base + brow[ni] + cxB[ks]));
            #pragma unroll
            for (int mi = 0; mi < 4; mi++) {
                uint32_t a0, a1, a2, a3;
                asm volatile("ldmatrix.sync.aligned.m8n8.x4.shared.b16 {%0,%1,%2,%3}, [%4];"
                             : "=r"(a0), "=r"(a1), "=r"(a2), "=r"(a3)
                             : "r"(base + arow[mi] + cxA[ks]));
                #pragma unroll
                for (int ni = 0; ni < 4; ni++)
                    asm volatile(
                        "mma.sync.aligned.m16n8k16.row.col.f32.f16.f16.f32 "
                        "{%0,%1,%2,%3}, {%4,%5,%6,%7}, {%8,%9}, {%0,%1,%2,%3};"
                        : "+f"(acc[mi][ni][0]), "+f"(acc[mi][ni][1]),
                          "+f"(acc[mi][ni][2]), "+f"(acc[mi][ni][3])
                        : "r"(a0), "r"(a1), "r"(a2), "r"(a3),
                          "r"(b0[ni]), "r"(b1[ni]));
            }
        }

        __syncthreads();                       // all warps done reading stage st
        if (tid == 0 && it + STAGES < KITERS) produce(it + STAGES, st);
        if (++st == STAGES) { st = 0; par ^= 1; }
    }

    // ------------- fused epilogue: acc -> SMEM -> gates -> outputs ---------
    __syncthreads();                           // pipeline fully drained
    float* sC = reinterpret_cast<float*>(smal);   // [128][132] fp32, 67.6 KB

    #pragma unroll
    for (int mi = 0; mi < 4; mi++) {
        const int r0 = wm * 64 + mi * 16 + (lane >> 2);
        #pragma unroll
        for (int ni = 0; ni < 4; ni++) {
            const int c0 = wn * 32 + ni * 8 + (lane & 3) * 2;
            *reinterpret_cast<float2*>(&sC[r0 * 132 + c0]) =
                make_float2(acc[mi][ni][0], acc[mi][ni][1]);
            *reinterpret_cast<float2*>(&sC[(r0 + 8) * 132 + c0]) =
                make_float2(acc[mi][ni][2], acc[mi][ni][3]);
        }
    }
    __syncthreads();

    const size_t mbase = (size_t)mtile * 128;
    const size_t hb    = (size_t)ntile * 32;

    #pragma unroll
    for (int kk = 0; kk < 16; kk++) {
        const int idx = kk * 256 + tid;
        const int m = idx >> 5, cc = idx & 31;
        const float gf = sC[m * 132 +       cc] + s_bias[cc];
        const float gi = sC[m * 132 +  32 + cc] + s_bias[32 + cc];
        const float gs = sC[m * 132 +  64 + cc] + s_bias[64 + cc];
        const float gg = sC[m * 132 +  96 + cc] + s_bias[96 + cc];

        const size_t off = (mbase + m) * 2048 + hb + cc;
        const float cin = Cin[off];

        const float f  = sigf(gf);
        const float ii = sigf(gi);
        const float ss = tanhf(gs);
        const float oo = sigf(gg);
        const float cn = f * cin + ii * ss;
        const float hn = oo * tanhf(cn);

        Oh[off] = hn;
        Oc[off] = cn;
        Og[off] = oo;
    }
}

// ============================================================================
// launch
// ============================================================================
extern "C" void kernel_launch(void* const* d_in, const int* in_sizes, int n_in,
                              void* d_out, int out_size)
{
    const float* x    = (const float*)d_in[0];
    const float* h    = (const float*)d_in[1];
    const float* c    = (const float*)d_in[2];
    /* d_in[3] = o, unused by the reference computation */
    const float* w_ih = (const float*)d_in[4];
    const float* w_hh = (const float*)d_in[5];
    const float* b    = (const float*)d_in[6];
    float* out = (float*)d_out;

    cudaFuncSetAttribute(lstm_gemm,
                         cudaFuncAttributeMaxDynamicSharedMemorySize, SMEM_ALLOC);

    cvt_pack<<<8192,  256>>>(x,    h,    0);
    cvt_pack<<<16384, 256>>>(w_ih, w_hh, 1);

    float* out_h  = out;
    float* out_c  = out + (size_t)4096 * 2048;
    float* out_go = out + (size_t)2 * 4096 * 2048;
    lstm_gemm<<<2048, 256, SMEM_ALLOC>>>(b, c, out_h, out_c, out_go);
}

// round 4
// speedup vs baseline: 1.0901x; 1.0780x over previous
#include <cuda_runtime.h>
#include <cuda_fp16.h>
#include <cstdint>

// ============================================================================
// LSTMCell for GB300 — sm_103 (non-'a') path: fp16 mma.sync + cp.async.bulk.
//
//   Pass 1 (single kernel): fp32 -> fp16 (RN), pre-tiled + SW128-swizzled.
//           A = [x|h]      as [32 mtile][64 kc][128 m][128B]
//           B = [Wih|Whh]  as [64 ntile][64 kc][128 packed-n][128B]
//           packed-n: n = gate*32 + col32 (each B tile is gate-complete).
//   Pass 2: GEMM 128x128x(BK=64) 3-stage bulk-copy pipeline,
//           B via ldmatrix.x4, fused fast-math LSTM epilogue.
// ============================================================================

#define DINLINE __device__ __forceinline__

__device__ __align__(1024) __half g_Ah[4096UL * 4096];   // 32 MB
__device__ __align__(1024) __half g_Bh[8192UL * 4096];   // 64 MB

// ------------------------------- helpers -----------------------------------
DINLINE uint32_t smem_u32(const void* p) {
    uint32_t a;
    asm("{ .reg .u64 t; cvta.to.shared.u64 t, %1; cvt.u32.u64 %0, t; }"
        : "=r"(a) : "l"(p));
    return a;
}

DINLINE void mbar_init(uint32_t a, uint32_t cnt) {
    asm volatile("mbarrier.init.shared.b64 [%0], %1;" :: "r"(a), "r"(cnt) : "memory");
}
DINLINE void mbar_expect(uint32_t a, uint32_t tx) {
    asm volatile("mbarrier.arrive.expect_tx.shared.b64 _, [%0], %1;"
                 :: "r"(a), "r"(tx) : "memory");
}
DINLINE void mbar_wait(uint32_t mbar, uint32_t parity) {
    uint32_t done;
    asm volatile(
        "{\n .reg .pred p;\n"
        " mbarrier.try_wait.parity.acquire.cta.shared::cta.b64 p, [%1], %2;\n"
        " selp.b32 %0, 1, 0, p;\n}"
        : "=r"(done) : "r"(mbar), "r"(parity) : "memory");
    if (!done) {
        asm volatile(
            "{\n .reg .pred P1;\n"
            "WL%=:\n"
            " mbarrier.try_wait.parity.acquire.cta.shared::cta.b64 P1, [%0], %1, 0x989680;\n"
            " @P1 bra.uni WD%=;\n"
            " bra.uni WL%=;\n"
            "WD%=:\n}"
            :: "r"(mbar), "r"(parity) : "memory");
    }
}

DINLINE void bulk_g2s(uint32_t dst, const void* src, uint32_t bytes, uint32_t mbar) {
    asm volatile(
        "cp.async.bulk.shared::cluster.global.mbarrier::complete_tx::bytes [%0], [%1], %2, [%3];"
        :: "r"(dst), "l"(src), "r"(bytes), "r"(mbar) : "memory");
}

// fast-math gates (ex2/rcp approx; errors ~1e-7, negligible vs fp16 inputs)
DINLINE float ex2a(float x) { float y; asm("ex2.approx.f32 %0, %1;" : "=f"(y) : "f"(x)); return y; }
DINLINE float rcpa(float x) { float y; asm("rcp.approx.f32 %0, %1;" : "=f"(y) : "f"(x)); return y; }
DINLINE float sigf(float x)  { return rcpa(1.0f + ex2a(-1.442695041f * x)); }
DINLINE float tanhp(float x) { return 2.0f * sigf(2.0f * x) - 1.0f; }

// ============================================================================
// Pass 1: convert + tile + swizzle.  Chunk = 16B of fp16 (8 halves).
//   chunk id bits: [c:3][m:7][kc:6][tile:rest]
//   A: 2^21 chunks, B: 2^22 chunks.  Each thread does 2 chunks (MLP=4 loads).
// ============================================================================
struct CvtIn { float4 v0, v1; };

DINLINE const float* chunk_src(const float* a, const float* b,
                               uint32_t t, int which)
{
    const uint32_t c = t & 7u;
    const uint32_t m = (t >> 3) & 127u;
    const uint32_t k = ((t >> 10) & 63u) * 64u + c * 8u;
    const uint32_t tile = t >> 16;
    uint32_t src_row;
    if (which) src_row = ((m >> 5) << 11) + tile * 32u + (m & 31u);
    else       src_row = tile * 128u + m;
    const size_t srow = (size_t)src_row * 2048;
    return (k < 2048u) ? (a + srow + k) : (b + srow + (k - 2048u));
}

DINLINE void chunk_store(__half* dstbuf, uint32_t t, const CvtIn& in)
{
    __half2 h0 = __floats2half2_rn(in.v0.x, in.v0.y);
    __half2 h1 = __floats2half2_rn(in.v0.z, in.v0.w);
    __half2 h2 = __floats2half2_rn(in.v1.x, in.v1.y);
    __half2 h3 = __floats2half2_rn(in.v1.z, in.v1.w);
    uint4 out;
    out.x = *reinterpret_cast<uint32_t*>(&h0);
    out.y = *reinterpret_cast<uint32_t*>(&h1);
    out.z = *reinterpret_cast<uint32_t*>(&h2);
    out.w = *reinterpret_cast<uint32_t*>(&h3);
    const uint32_t c = t & 7u, m = (t >> 3) & 127u;
    *reinterpret_cast<uint4*>((unsigned char*)dstbuf +
        ((size_t)(t >> 3) << 7) + ((c ^ (m & 7u)) << 4)) = out;
}

__global__ __launch_bounds__(256)
void cvt_pack(const float* __restrict__ x,  const float* __restrict__ h,
              const float* __restrict__ wi, const float* __restrict__ wh)
{
    const uint32_t g = blockIdx.x * 256u + threadIdx.x;
    if (g < (1u << 20)) {
        const uint32_t t0 = g, t1 = g + (1u << 20);
        const float* s0 = chunk_src(x, h, t0, 0);
        const float* s1 = chunk_src(x, h, t1, 0);
        CvtIn i0, i1;
        i0.v0 = *reinterpret_cast<const float4*>(s0);
        i0.v1 = *reinterpret_cast<const float4*>(s0 + 4);
        i1.v0 = *reinterpret_cast<const float4*>(s1);
        i1.v1 = *reinterpret_cast<const float4*>(s1 + 4);
        chunk_store(g_Ah, t0, i0);
        chunk_store(g_Ah, t1, i1);
    } else {
        const uint32_t q = g - (1u << 20);
        const uint32_t t0 = q, t1 = q + (1u << 21);
        const float* s0 = chunk_src(wi, wh, t0, 1);
        const float* s1 = chunk_src(wi, wh, t1, 1);
        CvtIn i0, i1;
        i0.v0 = *reinterpret_cast<const float4*>(s0);
        i0.v1 = *reinterpret_cast<const float4*>(s0 + 4);
        i1.v0 = *reinterpret_cast<const float4*>(s1);
        i1.v1 = *reinterpret_cast<const float4*>(s1 + 4);
        chunk_store(g_Bh, t0, i0);
        chunk_store(g_Bh, t1, i1);
    }
}

// ============================================================================
// Pass 2: fused GEMM + LSTM cell.
//   CTA tile 128(M) x 128(packed N = 4 gates x 32 h-cols), BK=64.
//   8 warps 2(M) x 4(N); warp tile 64x32; mma m16n8k16 fp16->fp32.
// ============================================================================
static constexpr int TILE_BYTES  = 16384;                 // 128 x 128B
static constexpr int STAGE_BYTES = 2 * TILE_BYTES;        // A + B
static constexpr int STAGES      = 3;
static constexpr int KITERS      = 64;                    // 4096 / 64
static constexpr int SMEM_ALLOC  = STAGES * STAGE_BYTES + 1024;

__global__ __launch_bounds__(256, 2)
void lstm_gemm(const float* __restrict__ Bv, const float* __restrict__ Cin,
               float* __restrict__ Oh, float* __restrict__ Oc, float* __restrict__ Og)
{
    extern __shared__ unsigned char smraw[];
    __shared__ __align__(8) unsigned long long mbar_s[STAGES];
    __shared__ float s_bias[128];

    const int tid  = threadIdx.x;
    const int lane = tid & 31;
    const int w    = tid >> 5;
    const int wm   = w & 1;        // 0..1  (M)
    const int wn   = w >> 1;       // 0..3  (N)
    const int mtile = blockIdx.x & 31;   // 0..31
    const int ntile = blockIdx.x >> 5;   // 0..63 (h-col block of 32)

    const uint32_t smb = (smem_u32(smraw) + 1023u) & ~1023u;
    unsigned char* smal = smraw + (smb - smem_u32(smraw));
    const uint32_t mbb = smem_u32(&mbar_s[0]);

    if (tid == 0) {
        mbar_init(mbb + 0, 1);
        mbar_init(mbb + 8, 1);
        mbar_init(mbb + 16, 1);
    }
    if (tid < 128)
        s_bias[tid] = Bv[(size_t)((tid >> 5) << 11) + (size_t)ntile * 32 + (tid & 31)];
    __syncthreads();

    const uint64_t gA = (uint64_t)(const void*)g_Ah + (uint64_t)(mtile * 64) * TILE_BYTES;
    const uint64_t gB = (uint64_t)(const void*)g_Bh + (uint64_t)(ntile * 64) * TILE_BYTES;

    auto produce = [&](int it, int st) {
        const uint32_t mb = mbb + st * 8;
        mbar_expect(mb, (uint32_t)STAGE_BYTES);
        bulk_g2s(smb + st * STAGE_BYTES,
                 (const void*)(gA + (uint64_t)it * TILE_BYTES), TILE_BYTES, mb);
        bulk_g2s(smb + st * STAGE_BYTES + TILE_BYTES,
                 (const void*)(gB + (uint64_t)it * TILE_BYTES), TILE_BYTES, mb);
    };
    if (tid == 0) { produce(0, 0); produce(1, 1); produce(2, 2); }

    // fragment address components (byte offsets inside a 16KB tile)
    uint32_t arow[4], brow4[2], cxA[4], cxB[4];
    #pragma unroll
    for (int mi = 0; mi < 4; mi++)
        arow[mi] = (uint32_t)((wm * 64 + mi * 16 + ((lane >> 3) & 1) * 8 + (lane & 7)) << 7);
    #pragma unroll
    for (int p = 0; p < 2; p++)   // ldmatrix.x4 covering n-frag pair (2p, 2p+1)
        brow4[p] = (uint32_t)(TILE_BYTES +
                   ((wn * 32 + p * 16 + ((lane >> 4) & 1) * 8 + (lane & 7)) << 7));
    #pragma unroll
    for (int ks = 0; ks < 4; ks++) {
        cxA[ks] = (uint32_t)((((2 * ks + (lane >> 4)) ^ (lane & 7)) << 4));
        cxB[ks] = (uint32_t)((((2 * ks + ((lane >> 3) & 1)) ^ (lane & 7)) << 4));
    }

    float acc[4][4][4];
    #pragma unroll
    for (int mi = 0; mi < 4; mi++)
        #pragma unroll
        for (int ni = 0; ni < 4; ni++)
            #pragma unroll
            for (int r = 0; r < 4; r++) acc[mi][ni][r] = 0.0f;

    int st = 0;
    uint32_t par = 0;

    for (int it = 0; it < KITERS; it++) {
        mbar_wait(mbb + st * 8, par);
        const uint32_t base = smb + st * STAGE_BYTES;

        #pragma unroll
        for (int ks = 0; ks < 4; ks++) {
            uint32_t b0[4], b1[4];
            #pragma unroll
            for (int p = 0; p < 2; p++)
                asm volatile("ldmatrix.sync.aligned.m8n8.x4.shared.b16 {%0,%1,%2,%3}, [%4];"
                             : "=r"(b0[2*p]), "=r"(b1[2*p]), "=r"(b0[2*p+1]), "=r"(b1[2*p+1])
                             : "r"(base + brow4[p] + cxB[ks]));
            #pragma unroll
            for (int mi = 0; mi < 4; mi++) {
                uint32_t a0, a1, a2, a3;
                asm volatile("ldmatrix.sync.aligned.m8n8.x4.shared.b16 {%0,%1,%2,%3}, [%4];"
                             : "=r"(a0), "=r"(a1), "=r"(a2), "=r"(a3)
                             : "r"(base + arow[mi] + cxA[ks]));
                #pragma unroll
                for (int ni = 0; ni < 4; ni++)
                    asm volatile(
                        "mma.sync.aligned.m16n8k16.row.col.f32.f16.f16.f32 "
                        "{%0,%1,%2,%3}, {%4,%5,%6,%7}, {%8,%9}, {%0,%1,%2,%3};"
                        : "+f"(acc[mi][ni][0]), "+f"(acc[mi][ni][1]),
                          "+f"(acc[mi][ni][2]), "+f"(acc[mi][ni][3])
                        : "r"(a0), "r"(a1), "r"(a2), "r"(a3),
                          "r"(b0[ni]), "r"(b1[ni]));
            }
        }

        __syncthreads();                       // all warps done reading stage st
        if (tid == 0 && it + STAGES < KITERS) produce(it + STAGES, st);
        if (++st == STAGES) { st = 0; par ^= 1; }
    }

    // ------------- fused epilogue: acc -> SMEM -> gates -> outputs ---------
    __syncthreads();
    float* sC = reinterpret_cast<float*>(smal);   // [128][132] fp32

    #pragma unroll
    for (int mi = 0; mi < 4; mi++) {
        const int r0 = wm * 64 + mi * 16 + (lane >> 2);
        #pragma unroll
        for (int ni = 0; ni < 4; ni++) {
            const int c0 = wn * 32 + ni * 8 + (lane & 3) * 2;
            *reinterpret_cast<float2*>(&sC[r0 * 132 + c0]) =
                make_float2(acc[mi][ni][0], acc[mi][ni][1]);
            *reinterpret_cast<float2*>(&sC[(r0 + 8) * 132 + c0]) =
                make_float2(acc[mi][ni][2], acc[mi][ni][3]);
        }
    }
    __syncthreads();

    const size_t mbase = (size_t)mtile * 128;
    const size_t hb    = (size_t)ntile * 32;

    #pragma unroll
    for (int kk = 0; kk < 16; kk++) {
        const int idx = kk * 256 + tid;
        const int m = idx >> 5, cc = idx & 31;
        const float gf = sC[m * 132 +       cc] + s_bias[cc];
        const float gi = sC[m * 132 +  32 + cc] + s_bias[32 + cc];
        const float gs = sC[m * 132 +  64 + cc] + s_bias[64 + cc];
        const float gg = sC[m * 132 +  96 + cc] + s_bias[96 + cc];

        const size_t off = (mbase + m) * 2048 + hb + cc;
        const float cin = Cin[off];

        const float f  = sigf(gf);
        const float ii = sigf(gi);
        const float ss = tanhp(gs);
        const float oo = sigf(gg);
        const float cn = f * cin + ii * ss;
        const float hn = oo * tanhp(cn);

        Oh[off] = hn;
        Oc[off] = cn;
        Og[off] = oo;
    }
}

// ============================================================================
// launch
// ============================================================================
extern "C" void kernel_launch(void* const* d_in, const int* in_sizes, int n_in,
                              void* d_out, int out_size)
{
    const float* x    = (const float*)d_in[0];
    const float* h    = (const float*)d_in[1];
    const float* c    = (const float*)d_in[2];
    /* d_in[3] = o, unused by the reference computation */
    const float* w_ih = (const float*)d_in[4];
    const float* w_hh = (const float*)d_in[5];
    const float* b    = (const float*)d_in[6];
    float* out = (float*)d_out;

    cudaFuncSetAttribute(lstm_gemm,
                         cudaFuncAttributeMaxDynamicSharedMemorySize, SMEM_ALLOC);

    cvt_pack<<<12288, 256>>>(x, h, w_ih, w_hh);

    float* out_h  = out;
    float* out_c  = out + (size_t)4096 * 2048;
    float* out_go = out + (size_t)2 * 4096 * 2048;
    lstm_gemm<<<2048, 256, SMEM_ALLOC>>>(b, c, out_h, out_c, out_go);
}

// round 5
// speedup vs baseline: 1.1202x; 1.0276x over previous
#include <cuda_runtime.h>
#include <cuda_fp16.h>
#include <cstdint>

// ============================================================================
// LSTMCell for GB300 — sm_103 (non-'a') path: fp16 mma.sync + cp.async.bulk.
//
//   Pass 1 (single kernel): fp32 -> fp16 (RN), pre-tiled + SW128-swizzled.
//   Pass 2: GEMM 128x128x(BK=64), 3-stage bulk-copy pipeline with
//           producer/consumer mbarrier ring (NO per-iter __syncthreads),
//           B via ldmatrix.x4, fused fast-math LSTM epilogue w/ Cin prefetch.
// ============================================================================

#define DINLINE __device__ __forceinline__

__device__ __align__(1024) __half g_Ah[4096UL * 4096];   // 32 MB
__device__ __align__(1024) __half g_Bh[8192UL * 4096];   // 64 MB

// ------------------------------- helpers -----------------------------------
DINLINE uint32_t smem_u32(const void* p) {
    uint32_t a;
    asm("{ .reg .u64 t; cvta.to.shared.u64 t, %1; cvt.u32.u64 %0, t; }"
        : "=r"(a) : "l"(p));
    return a;
}

DINLINE void mbar_init(uint32_t a, uint32_t cnt) {
    asm volatile("mbarrier.init.shared.b64 [%0], %1;" :: "r"(a), "r"(cnt) : "memory");
}
DINLINE void mbar_expect(uint32_t a, uint32_t tx) {
    asm volatile("mbarrier.arrive.expect_tx.shared.b64 _, [%0], %1;"
                 :: "r"(a), "r"(tx) : "memory");
}
DINLINE void mbar_arrive(uint32_t a) {
    asm volatile("mbarrier.arrive.shared.b64 _, [%0];" :: "r"(a) : "memory");
}
DINLINE void mbar_wait(uint32_t mbar, uint32_t parity) {
    uint32_t done;
    asm volatile(
        "{\n .reg .pred p;\n"
        " mbarrier.try_wait.parity.acquire.cta.shared::cta.b64 p, [%1], %2;\n"
        " selp.b32 %0, 1, 0, p;\n}"
        : "=r"(done) : "r"(mbar), "r"(parity) : "memory");
    if (!done) {
        asm volatile(
            "{\n .reg .pred P1;\n"
            "WL%=:\n"
            " mbarrier.try_wait.parity.acquire.cta.shared::cta.b64 P1, [%0], %1, 0x989680;\n"
            " @P1 bra.uni WD%=;\n"
            " bra.uni WL%=;\n"
            "WD%=:\n}"
            :: "r"(mbar), "r"(parity) : "memory");
    }
}

DINLINE void bulk_g2s(uint32_t dst, const void* src, uint32_t bytes, uint32_t mbar) {
    asm volatile(
        "cp.async.bulk.shared::cluster.global.mbarrier::complete_tx::bytes [%0], [%1], %2, [%3];"
        :: "r"(dst), "l"(src), "r"(bytes), "r"(mbar) : "memory");
}

// fast-math gates (ex2/rcp approx; errors ~1e-7, negligible vs fp16 inputs)
DINLINE float ex2a(float x) { float y; asm("ex2.approx.f32 %0, %1;" : "=f"(y) : "f"(x)); return y; }
DINLINE float rcpa(float x) { float y; asm("rcp.approx.f32 %0, %1;" : "=f"(y) : "f"(x)); return y; }
DINLINE float sigf(float x)  { return rcpa(1.0f + ex2a(-1.442695041f * x)); }
DINLINE float tanhp(float x) { return 2.0f * sigf(2.0f * x) - 1.0f; }

// ============================================================================
// Pass 1: convert + tile + swizzle.  Chunk = 16B of fp16 (8 halves).
// ============================================================================
struct CvtIn { float4 v0, v1; };

DINLINE const float* chunk_src(const float* a, const float* b,
                               uint32_t t, int which)
{
    const uint32_t c = t & 7u;
    const uint32_t m = (t >> 3) & 127u;
    const uint32_t k = ((t >> 10) & 63u) * 64u + c * 8u;
    const uint32_t tile = t >> 16;
    uint32_t src_row;
    if (which) src_row = ((m >> 5) << 11) + tile * 32u + (m & 31u);
    else       src_row = tile * 128u + m;
    const size_t srow = (size_t)src_row * 2048;
    return (k < 2048u) ? (a + srow + k) : (b + srow + (k - 2048u));
}

DINLINE void chunk_store(__half* dstbuf, uint32_t t, const CvtIn& in)
{
    __half2 h0 = __floats2half2_rn(in.v0.x, in.v0.y);
    __half2 h1 = __floats2half2_rn(in.v0.z, in.v0.w);
    __half2 h2 = __floats2half2_rn(in.v1.x, in.v1.y);
    __half2 h3 = __floats2half2_rn(in.v1.z, in.v1.w);
    uint4 out;
    out.x = *reinterpret_cast<uint32_t*>(&h0);
    out.y = *reinterpret_cast<uint32_t*>(&h1);
    out.z = *reinterpret_cast<uint32_t*>(&h2);
    out.w = *reinterpret_cast<uint32_t*>(&h3);
    const uint32_t c = t & 7u, m = (t >> 3) & 127u;
    *reinterpret_cast<uint4*>((unsigned char*)dstbuf +
        ((size_t)(t >> 3) << 7) + ((c ^ (m & 7u)) << 4)) = out;
}

__global__ __launch_bounds__(256)
void cvt_pack(const float* __restrict__ x,  const float* __restrict__ h,
              const float* __restrict__ wi, const float* __restrict__ wh)
{
    const uint32_t g = blockIdx.x * 256u + threadIdx.x;
    if (g < (1u << 20)) {
        const uint32_t t0 = g, t1 = g + (1u << 20);
        const float* s0 = chunk_src(x, h, t0, 0);
        const float* s1 = chunk_src(x, h, t1, 0);
        CvtIn i0, i1;
        i0.v0 = *reinterpret_cast<const float4*>(s0);
        i0.v1 = *reinterpret_cast<const float4*>(s0 + 4);
        i1.v0 = *reinterpret_cast<const float4*>(s1);
        i1.v1 = *reinterpret_cast<const float4*>(s1 + 4);
        chunk_store(g_Ah, t0, i0);
        chunk_store(g_Ah, t1, i1);
    } else {
        const uint32_t q = g - (1u << 20);
        const uint32_t t0 = q, t1 = q + (1u << 21);
        const float* s0 = chunk_src(wi, wh, t0, 1);
        const float* s1 = chunk_src(wi, wh, t1, 1);
        CvtIn i0, i1;
        i0.v0 = *reinterpret_cast<const float4*>(s0);
        i0.v1 = *reinterpret_cast<const float4*>(s0 + 4);
        i1.v0 = *reinterpret_cast<const float4*>(s1);
        i1.v1 = *reinterpret_cast<const float4*>(s1 + 4);
        chunk_store(g_Bh, t0, i0);
        chunk_store(g_Bh, t1, i1);
    }
}

// ============================================================================
// Pass 2: fused GEMM + LSTM cell.
//   CTA tile 128(M) x 128(packed N = 4 gates x 32 h-cols), BK=64.
//   8 warps 2(M) x 4(N); warp tile 64x32; mma m16n8k16 fp16->fp32.
//   Pipeline: full[s] (tx mbarrier) + empty[s] (count-256 mbarrier) ring.
// ============================================================================
static constexpr int TILE_BYTES  = 16384;                 // 128 x 128B
static constexpr int STAGE_BYTES = 2 * TILE_BYTES;        // A + B
static constexpr int STAGES      = 3;
static constexpr int KITERS      = 64;                    // 4096 / 64
static constexpr int SMEM_ALLOC  = STAGES * STAGE_BYTES + 1024;

__global__ __launch_bounds__(256, 2)
void lstm_gemm(const float* __restrict__ Bv, const float* __restrict__ Cin,
               float* __restrict__ Oh, float* __restrict__ Oc, float* __restrict__ Og)
{
    extern __shared__ unsigned char smraw[];
    __shared__ __align__(8) unsigned long long mbar_s[2 * STAGES];  // full[3], empty[3]
    __shared__ float s_bias[128];

    const int tid  = threadIdx.x;
    const int lane = tid & 31;
    const int w    = tid >> 5;
    const int wm   = w & 1;        // 0..1  (M)
    const int wn   = w >> 1;       // 0..3  (N)
    const int mtile = blockIdx.x & 31;   // 0..31
    const int ntile = blockIdx.x >> 5;   // 0..63 (h-col block of 32)

    const uint32_t smb = (smem_u32(smraw) + 1023u) & ~1023u;
    unsigned char* smal = smraw + (smb - smem_u32(smraw));
    const uint32_t mbb = smem_u32(&mbar_s[0]);     // full[s]  at mbb + s*8
    const uint32_t ebb = mbb + STAGES * 8;         // empty[s] at ebb + s*8

    if (tid == 0) {
        #pragma unroll
        for (int s = 0; s < STAGES; s++) {
            mbar_init(mbb + s * 8, 1);
            mbar_init(ebb + s * 8, 256);
        }
    }
    if (tid < 128)
        s_bias[tid] = Bv[(size_t)((tid >> 5) << 11) + (size_t)ntile * 32 + (tid & 31)];
    __syncthreads();

    const uint64_t gA = (uint64_t)(const void*)g_Ah + (uint64_t)(mtile * 64) * TILE_BYTES;
    const uint64_t gB = (uint64_t)(const void*)g_Bh + (uint64_t)(ntile * 64) * TILE_BYTES;

    auto produce = [&](int it, int st) {
        const uint32_t mb = mbb + st * 8;
        mbar_expect(mb, (uint32_t)STAGE_BYTES);
        bulk_g2s(smb + st * STAGE_BYTES,
                 (const void*)(gA + (uint64_t)it * TILE_BYTES), TILE_BYTES, mb);
        bulk_g2s(smb + st * STAGE_BYTES + TILE_BYTES,
                 (const void*)(gB + (uint64_t)it * TILE_BYTES), TILE_BYTES, mb);
    };
    if (tid == 0) { produce(0, 0); produce(1, 1); produce(2, 2); }

    // fragment address components (byte offsets inside a 16KB tile)
    uint32_t arow[4], brow4[2], cxA[4], cxB[4];
    #pragma unroll
    for (int mi = 0; mi < 4; mi++)
        arow[mi] = (uint32_t)((wm * 64 + mi * 16 + ((lane >> 3) & 1) * 8 + (lane & 7)) << 7);
    #pragma unroll
    for (int p = 0; p < 2; p++)   // ldmatrix.x4 covering n-frag pair (2p, 2p+1)
        brow4[p] = (uint32_t)(TILE_BYTES +
                   ((wn * 32 + p * 16 + ((lane >> 4) & 1) * 8 + (lane & 7)) << 7));
    #pragma unroll
    for (int ks = 0; ks < 4; ks++) {
        cxA[ks] = (uint32_t)((((2 * ks + (lane >> 4)) ^ (lane & 7)) << 4));
        cxB[ks] = (uint32_t)((((2 * ks + ((lane >> 3) & 1)) ^ (lane & 7)) << 4));
    }

    float acc[4][4][4];
    #pragma unroll
    for (int mi = 0; mi < 4; mi++)
        #pragma unroll
        for (int ni = 0; ni < 4; ni++)
            #pragma unroll
            for (int r = 0; r < 4; r++) acc[mi][ni][r] = 0.0f;

    // ring state: at iteration it, parity for full-wait and empty-wait is
    // (it / STAGES) & 1, tracked incrementally via `trip`.
    int st = 0;
    uint32_t trip = 0;

    for (int it = 0; it < KITERS; it++) {
        const uint32_t par = trip & 1u;
        mbar_wait(mbb + st * 8, par);
        const uint32_t base = smb + st * STAGE_BYTES;

        #pragma unroll
        for (int ks = 0; ks < 4; ks++) {
            uint32_t b0[4], b1[4];
            #pragma unroll
            for (int p = 0; p < 2; p++)
                asm volatile("ldmatrix.sync.aligned.m8n8.x4.shared.b16 {%0,%1,%2,%3}, [%4];"
                             : "=r"(b0[2*p]), "=r"(b1[2*p]), "=r"(b0[2*p+1]), "=r"(b1[2*p+1])
                             : "r"(base + brow4[p] + cxB[ks]));
            #pragma unroll
            for (int mi = 0; mi < 4; mi++) {
                uint32_t a0, a1, a2, a3;
                asm volatile("ldmatrix.sync.aligned.m8n8.x4.shared.b16 {%0,%1,%2,%3}, [%4];"
                             : "=r"(a0), "=r"(a1), "=r"(a2), "=r"(a3)
                             : "r"(base + arow[mi] + cxA[ks]));
                #pragma unroll
                for (int ni = 0; ni < 4; ni++)
                    asm volatile(
                        "mma.sync.aligned.m16n8k16.row.col.f32.f16.f16.f32 "
                        "{%0,%1,%2,%3}, {%4,%5,%6,%7}, {%8,%9}, {%0,%1,%2,%3};"
                        : "+f"(acc[mi][ni][0]), "+f"(acc[mi][ni][1]),
                          "+f"(acc[mi][ni][2]), "+f"(acc[mi][ni][3])
                        : "r"(a0), "r"(a1), "r"(a2), "r"(a3),
                          "r"(b0[ni]), "r"(b1[ni]));
            }
        }

        // this thread is done reading stage st (LDSM results in registers)
        mbar_arrive(ebb + st * 8);

        // producer: refill st for iteration it+STAGES once ALL threads arrived
        if (tid == 0 && it + STAGES < KITERS) {
            mbar_wait(ebb + st * 8, trip & 1u);
            produce(it + STAGES, st);
        }

        if (++st == STAGES) { st = 0; trip++; }
    }

    // ------------- fused epilogue: acc -> SMEM -> gates -> outputs ---------
    __syncthreads();                               // pipeline fully drained
    float* sC = reinterpret_cast<float*>(smal);    // [128][132] fp32

    const size_t mbase = (size_t)mtile * 128;
    const size_t hb    = (size_t)ntile * 32;

    // prefetch Cin (overlaps with acc->SMEM transpose + barrier)
    float cin[16];
    #pragma unroll
    for (int kk = 0; kk < 16; kk++) {
        const int idx = kk * 256 + tid;
        const int m = idx >> 5, cc = idx & 31;
        cin[kk] = Cin[(mbase + m) * 2048 + hb + cc];
    }

    #pragma unroll
    for (int mi = 0; mi < 4; mi++) {
        const int r0 = wm * 64 + mi * 16 + (lane >> 2);
        #pragma unroll
        for (int ni = 0; ni < 4; ni++) {
            const int c0 = wn * 32 + ni * 8 + (lane & 3) * 2;
            *reinterpret_cast<float2*>(&sC[r0 * 132 + c0]) =
                make_float2(acc[mi][ni][0], acc[mi][ni][1]);
            *reinterpret_cast<float2*>(&sC[(r0 + 8) * 132 + c0]) =
                make_float2(acc[mi][ni][2], acc[mi][ni][3]);
        }
    }
    __syncthreads();

    #pragma unroll
    for (int kk = 0; kk < 16; kk++) {
        const int idx = kk * 256 + tid;
        const int m = idx >> 5, cc = idx & 31;
        const float gf = sC[m * 132 +       cc] + s_bias[cc];
        const float gi = sC[m * 132 +  32 + cc] + s_bias[32 + cc];
        const float gs = sC[m * 132 +  64 + cc] + s_bias[64 + cc];
        const float gg = sC[m * 132 +  96 + cc] + s_bias[96 + cc];

        const float f  = sigf(gf);
        const float ii = sigf(gi);
        const float ss = tanhp(gs);
        const float oo = sigf(gg);
        const float cn = f * cin[kk] + ii * ss;
        const float hn = oo * tanhp(cn);

        const size_t off = (mbase + m) * 2048 + hb + cc;
        Oh[off] = hn;
        Oc[off] = cn;
        Og[off] = oo;
    }
}

// ============================================================================
// launch
// ============================================================================
extern "C" void kernel_launch(void* const* d_in, const int* in_sizes, int n_in,
                              void* d_out, int out_size)
{
    const float* x    = (const float*)d_in[0];
    const float* h    = (const float*)d_in[1];
    const float* c    = (const float*)d_in[2];
    /* d_in[3] = o, unused by the reference computation */
    const float* w_ih = (const float*)d_in[4];
    const float* w_hh = (const float*)d_in[5];
    const float* b    = (const float*)d_in[6];
    float* out = (float*)d_out;

    cudaFuncSetAttribute(lstm_gemm,
                         cudaFuncAttributeMaxDynamicSharedMemorySize, SMEM_ALLOC);

    cvt_pack<<<12288, 256>>>(x, h, w_ih, w_hh);

    float* out_h  = out;
    float* out_c  = out + (size_t)4096 * 2048;
    float* out_go = out + (size_t)2 * 4096 * 2048;
    lstm_gemm<<<2048, 256, SMEM_ALLOC>>>(b, c, out_h, out_c, out_go);
}